// round 1
// baseline (speedup 1.0000x reference)
#include <cuda_runtime.h>
#include <cstdint>

#define Bv 128
#define Sv 1024
#define Fv 512
#define Hv 128
#define G3 (3*Hv)

// ---------------- scratch (static device arrays; no allocation) ----------------
__device__ float g_xg[(size_t)Bv * Sv * G3];     // xg0, later reused for xg1
__device__ float g_proj[(size_t)Bv * Sv * Hv];   // proj, later reused for h1
__device__ int   g_len[Bv];
__device__ int   g_rank[Bv];

// ---------------- f32x2 helpers (Blackwell packed fp32) ----------------
static __device__ __forceinline__ unsigned long long pk2(float x, float y) {
    unsigned long long r;
    asm("mov.b64 %0, {%1, %2};" : "=l"(r) : "f"(x), "f"(y));
    return r;
}
static __device__ __forceinline__ unsigned long long dup2(float x) {
    unsigned long long r;
    asm("mov.b64 %0, {%1, %1};" : "=l"(r) : "f"(x));
    return r;
}
static __device__ __forceinline__ void fma2p(unsigned long long &d,
                                             unsigned long long a,
                                             unsigned long long b) {
    asm("fma.rn.f32x2 %0, %1, %2, %0;" : "+l"(d) : "l"(a), "l"(b));
}
static __device__ __forceinline__ float2 upk(unsigned long long v) {
    float2 f;
    asm("mov.b64 {%0, %1}, %2;" : "=f"(f.x), "=f"(f.y) : "l"(v));
    return f;
}
static __device__ __forceinline__ float fsig(float x) {
    return __fdividef(1.0f, 1.0f + __expf(-x));
}
static __device__ __forceinline__ float ftanh(float x) {
    float e = __expf(2.0f * x);
    return 1.0f - __fdividef(2.0f, e + 1.0f);
}

// ---------------- lengths: count nonzero rows per batch ----------------
__global__ void lengths_kernel(const float* __restrict__ x, int* __restrict__ len) {
    const int b = blockIdx.x;
    const int warp = threadIdx.x >> 5, lane = threadIdx.x & 31;
    __shared__ int cnt;
    if (threadIdx.x == 0) cnt = 0;
    __syncthreads();
    int local = 0;
    for (int s = warp; s < Sv; s += 8) {  // 256 threads = 8 warps
        // valid rows are iid normals: checking first 64 elems suffices (exact-zero prob ~0)
        const float2* row = (const float2*)(x + ((size_t)b * Sv + s) * Fv);
        float2 v = row[lane];
        bool nz = (v.x != 0.0f) || (v.y != 0.0f);
        if (__any_sync(0xffffffffu, nz)) local++;
    }
    if (lane == 0) atomicAdd(&cnt, local);
    __syncthreads();
    if (threadIdx.x == 0) len[b] = cnt;
}

// ---------------- stable-descending rank ----------------
__global__ void rank_kernel(const int* __restrict__ len, int* __restrict__ rank) {
    const int b = threadIdx.x;
    const int L = len[b];
    int r = 0;
    for (int j = 0; j < Bv; j++) {
        int Lj = len[j];
        r += (Lj > L) || (Lj == L && j < b);
    }
    rank[b] = r;
}

// ---------------- GEMM: C[m,n] = sum_k A[m,k]*W[n,k] + bias[n] ----------------
// M = Bv*Sv (grid.x * 128), N in {128, 384}, K in {512, 128}. BM=BN=128, BK=16.
__global__ void __launch_bounds__(256, 2) gemm_nt_bias(
    const float* __restrict__ A, const float* __restrict__ W,
    const float* __restrict__ bias, float* __restrict__ C,
    int K, int N)
{
    __shared__ __align__(16) float As[2][16][128];
    __shared__ __align__(16) float Ws[2][16][128];

    const int tid = threadIdx.x;
    const int m0 = blockIdx.x * 128;
    const int n0 = blockIdx.y * 128;
    const int tx = tid & 15;     // n micro-tile
    const int ty = tid >> 4;     // m micro-tile
    const int lrow = tid >> 1;   // loader row 0..127
    const int lk = (tid & 1) * 8;

    const float* Ap = A + (size_t)(m0 + lrow) * K + lk;
    const float* Wpg = W + (size_t)(n0 + lrow) * K + lk;

    unsigned long long acc[8][4];
#pragma unroll
    for (int i = 0; i < 8; i++)
#pragma unroll
        for (int j = 0; j < 4; j++) acc[i][j] = 0ull;

    const int nst = K >> 4;
    float4 ra0, ra1, rw0, rw1;
    ra0 = *(const float4*)(Ap);     ra1 = *(const float4*)(Ap + 4);
    rw0 = *(const float4*)(Wpg);    rw1 = *(const float4*)(Wpg + 4);

    auto sts = [&](int buf) {
        As[buf][lk + 0][lrow] = ra0.x; As[buf][lk + 1][lrow] = ra0.y;
        As[buf][lk + 2][lrow] = ra0.z; As[buf][lk + 3][lrow] = ra0.w;
        As[buf][lk + 4][lrow] = ra1.x; As[buf][lk + 5][lrow] = ra1.y;
        As[buf][lk + 6][lrow] = ra1.z; As[buf][lk + 7][lrow] = ra1.w;
        Ws[buf][lk + 0][lrow] = rw0.x; Ws[buf][lk + 1][lrow] = rw0.y;
        Ws[buf][lk + 2][lrow] = rw0.z; Ws[buf][lk + 3][lrow] = rw0.w;
        Ws[buf][lk + 4][lrow] = rw1.x; Ws[buf][lk + 5][lrow] = rw1.y;
        Ws[buf][lk + 6][lrow] = rw1.z; Ws[buf][lk + 7][lrow] = rw1.w;
    };

    sts(0);
    __syncthreads();

    for (int ks = 0; ks < nst; ks++) {
        const int cur = ks & 1;
        if (ks + 1 < nst) {
            const float* a2 = Ap + (ks + 1) * 16;
            const float* w2 = Wpg + (ks + 1) * 16;
            ra0 = *(const float4*)a2;  ra1 = *(const float4*)(a2 + 4);
            rw0 = *(const float4*)w2;  rw1 = *(const float4*)(w2 + 4);
        }
#pragma unroll
        for (int k = 0; k < 16; k++) {
            float4 a0 = *(const float4*)&As[cur][k][ty * 8];
            float4 a1 = *(const float4*)&As[cur][k][ty * 8 + 4];
            float4 b0 = *(const float4*)&Ws[cur][k][tx * 8];
            float4 b1 = *(const float4*)&Ws[cur][k][tx * 8 + 4];
            unsigned long long bb0 = pk2(b0.x, b0.y), bb1 = pk2(b0.z, b0.w);
            unsigned long long bb2 = pk2(b1.x, b1.y), bb3 = pk2(b1.z, b1.w);
            float av[8] = {a0.x, a0.y, a0.z, a0.w, a1.x, a1.y, a1.z, a1.w};
#pragma unroll
            for (int i = 0; i < 8; i++) {
                unsigned long long ad = dup2(av[i]);
                fma2p(acc[i][0], ad, bb0);
                fma2p(acc[i][1], ad, bb1);
                fma2p(acc[i][2], ad, bb2);
                fma2p(acc[i][3], ad, bb3);
            }
        }
        if (ks + 1 < nst) {
            sts(cur ^ 1);
            __syncthreads();
        }
    }

    float bs[8];
#pragma unroll
    for (int j = 0; j < 8; j++) bs[j] = bias[n0 + tx * 8 + j];
#pragma unroll
    for (int i = 0; i < 8; i++) {
        float2 p0 = upk(acc[i][0]), p1 = upk(acc[i][1]);
        float2 p2 = upk(acc[i][2]), p3 = upk(acc[i][3]);
        float4 o0 = make_float4(p0.x + bs[0], p0.y + bs[1], p1.x + bs[2], p1.y + bs[3]);
        float4 o1 = make_float4(p2.x + bs[4], p2.y + bs[5], p3.x + bs[6], p3.y + bs[7]);
        float* cp = C + (size_t)(m0 + ty * 8 + i) * N + n0 + tx * 8;
        *(float4*)cp = o0;
        *(float4*)(cp + 4) = o1;
    }
}

// ---------------- GRU recurrence: one CTA per sequence ----------------
// 384 threads, thread g owns Whh[g, 0:128] in registers (64 x f32x2).
// Per step: hg[g] = bhh[g] + dot(h, Whh[g,:]) via fma.rn.f32x2; 128 combiner
// threads apply gate math. xg is prefetched 2 steps ahead through registers.
template <bool LAST>
__global__ void __launch_bounds__(384, 1) gru_layer_kernel(
    const float* __restrict__ xg,   // [Bv,Sv,3H]
    const float* __restrict__ Whh,  // [3H,H]
    const float* __restrict__ bhh,  // [3H]
    const int* __restrict__ len,
    float* __restrict__ h_out,      // [Bv,Sv,H] when !LAST
    float* __restrict__ out,        // [Bv,H] when LAST (sorted order)
    const int* __restrict__ rank)
{
    const int b = blockIdx.x;
    const int g = threadIdx.x;

    __shared__ __align__(16) float h_sh[Hv];
    __shared__ __align__(16) float hg_sh[G3];
    __shared__ __align__(16) float xg_sh[2][G3];

    // weight preload into registers
    unsigned long long w[64];
    {
        const float4* wp = (const float4*)(Whh + (size_t)g * Hv);
#pragma unroll
        for (int i = 0; i < 32; i++) {
            float4 v = wp[i];
            w[2 * i]     = pk2(v.x, v.y);
            w[2 * i + 1] = pk2(v.z, v.w);
        }
    }
    const float bh = bhh[g];
    const int L = len[b];
    const float* xb = xg + (size_t)b * Sv * G3;

    if (g < Hv) h_sh[g] = 0.0f;
    float xB = (L > 1) ? xb[(size_t)G3 + g] : 0.0f;   // x_{1}
    xg_sh[0][g] = (L > 0) ? xb[g] : 0.0f;             // x_{0}
    __syncthreads();

    float oacc = 0.0f;

    for (int s = 0; s < L; s++) {
        const int cur = s & 1;
        float xN = (s + 2 < L) ? xb[(size_t)(s + 2) * G3 + g] : 0.0f;  // x_{s+2}

        unsigned long long a0 = pk2(bh, 0.0f);
        unsigned long long a1 = 0ull;
        const unsigned long long* hp = (const unsigned long long*)h_sh;
#pragma unroll
        for (int i = 0; i < 32; i++) {
            fma2p(a0, w[2 * i],     hp[2 * i]);
            fma2p(a1, w[2 * i + 1], hp[2 * i + 1]);
        }
        float2 f0 = upk(a0), f1 = upk(a1);
        hg_sh[g] = (f0.x + f1.x) + (f0.y + f1.y);
        xg_sh[cur ^ 1][g] = xB;   // stage x_{s+1}
        __syncthreads();

        if (g < Hv) {
            float xr = xg_sh[cur][g], xz = xg_sh[cur][g + Hv], xn = xg_sh[cur][g + 2 * Hv];
            float hr = hg_sh[g], hz = hg_sh[g + Hv], hn = hg_sh[g + 2 * Hv];
            float r = fsig(xr + hr);
            float z = fsig(xz + hz);
            float n = ftanh(xn + r * hn);
            float hprev = h_sh[g];
            float hnew = n + z * (hprev - n);  // (1-z)*n + z*h
            h_sh[g] = hnew;
            if (!LAST) {
                h_out[((size_t)b * Sv + s) * Hv + g] = hnew;
            } else {
                oacc += hnew;
            }
        }
        __syncthreads();
        xB = xN;
    }

    if (LAST && g < Hv) {
        out[(size_t)rank[b] * Hv + g] = oacc * (1.0f / (float)Sv);
    }
}

// ---------------- launch ----------------
extern "C" void kernel_launch(void* const* d_in, const int* in_sizes, int n_in,
                              void* d_out, int out_size) {
    (void)in_sizes; (void)n_in; (void)out_size;
    const float* x    = (const float*)d_in[0];
    const float* Wp   = (const float*)d_in[1];
    const float* bp   = (const float*)d_in[2];
    const float* Wih0 = (const float*)d_in[3];
    const float* Whh0 = (const float*)d_in[4];
    const float* bih0 = (const float*)d_in[5];
    const float* bhh0 = (const float*)d_in[6];
    const float* Wih1 = (const float*)d_in[7];
    const float* Whh1 = (const float*)d_in[8];
    const float* bih1 = (const float*)d_in[9];
    const float* bhh1 = (const float*)d_in[10];
    float* out = (float*)d_out;

    float *xg, *proj;
    int *len, *rank;
    cudaGetSymbolAddress((void**)&xg, g_xg);
    cudaGetSymbolAddress((void**)&proj, g_proj);
    cudaGetSymbolAddress((void**)&len, g_len);
    cudaGetSymbolAddress((void**)&rank, g_rank);

    const int M = Bv * Sv;

    lengths_kernel<<<Bv, 256>>>(x, len);
    rank_kernel<<<1, Bv>>>(len, rank);
    // proj = x @ Wp^T + bp        [M,512] x [128,512] -> [M,128]
    gemm_nt_bias<<<dim3(M / 128, Hv / 128), 256>>>(x, Wp, bp, proj, Fv, Hv);
    // xg0 = proj @ Wih0^T + bih0  [M,128] x [384,128] -> [M,384]
    gemm_nt_bias<<<dim3(M / 128, G3 / 128), 256>>>(proj, Wih0, bih0, xg, Hv, G3);
    // layer 0 recurrence: writes h1 into proj buffer (proj no longer needed)
    gru_layer_kernel<false><<<Bv, 384>>>(xg, Whh0, bhh0, len, proj, nullptr, nullptr);
    // xg1 = h1 @ Wih1^T + bih1
    gemm_nt_bias<<<dim3(M / 128, G3 / 128), 256>>>(proj, Wih1, bih1, xg, Hv, G3);
    // layer 1 recurrence: accumulates masked mean, scatters by rank
    gru_layer_kernel<true><<<Bv, 384>>>(xg, Whh1, bhh1, len, nullptr, out, rank);
}

// round 2
// speedup vs baseline: 1.0664x; 1.0664x over previous
#include <cuda_runtime.h>
#include <cstdint>

#define Bv 128
#define Sv 1024
#define Fv 512
#define Hv 128
#define G3 (3*Hv)

typedef unsigned long long ull;

// ---------------- scratch (static device arrays; no allocation) ----------------
__device__ float g_xg[(size_t)Bv * Sv * G3];     // xg0, later reused for xg1
__device__ float g_proj[(size_t)Bv * Sv * Hv];   // proj, later reused for h1
__device__ int   g_len[Bv];
__device__ int   g_rank[Bv];

// ---------------- f32x2 helpers (Blackwell packed fp32) ----------------
static __device__ __forceinline__ ull pk2(float x, float y) {
    ull r;
    asm("mov.b64 %0, {%1, %2};" : "=l"(r) : "f"(x), "f"(y));
    return r;
}
static __device__ __forceinline__ ull dup2(float x) {
    ull r;
    asm("mov.b64 %0, {%1, %1};" : "=l"(r) : "f"(x));
    return r;
}
static __device__ __forceinline__ void fma2p(ull &d, ull a, ull b) {
    asm("fma.rn.f32x2 %0, %1, %2, %0;" : "+l"(d) : "l"(a), "l"(b));
}
static __device__ __forceinline__ float2 upk(ull v) {
    float2 f;
    asm("mov.b64 {%0, %1}, %2;" : "=f"(f.x), "=f"(f.y) : "l"(v));
    return f;
}
static __device__ __forceinline__ float fsig(float x) {
    return __fdividef(1.0f, 1.0f + __expf(-x));
}
static __device__ __forceinline__ float ftanh(float x) {
    float e = __expf(2.0f * x);
    return 1.0f - __fdividef(2.0f, e + 1.0f);
}

// ---------------- lengths: count nonzero rows per batch ----------------
__global__ void lengths_kernel(const float* __restrict__ x, int* __restrict__ len) {
    const int b = blockIdx.x;
    const int warp = threadIdx.x >> 5, lane = threadIdx.x & 31;
    __shared__ int cnt;
    if (threadIdx.x == 0) cnt = 0;
    __syncthreads();
    int local = 0;
    for (int s = warp; s < Sv; s += 8) {
        const float2* row = (const float2*)(x + ((size_t)b * Sv + s) * Fv);
        float2 v = row[lane];
        bool nz = (v.x != 0.0f) || (v.y != 0.0f);
        if (__any_sync(0xffffffffu, nz)) local++;
    }
    if (lane == 0) atomicAdd(&cnt, local);
    __syncthreads();
    if (threadIdx.x == 0) len[b] = cnt;
}

// ---------------- stable-descending rank ----------------
__global__ void rank_kernel(const int* __restrict__ len, int* __restrict__ rank) {
    const int b = threadIdx.x;
    const int L = len[b];
    int r = 0;
    for (int j = 0; j < Bv; j++) {
        int Lj = len[j];
        r += (Lj > L) || (Lj == L && j < b);
    }
    rank[b] = r;
}

// ---------------- GEMM: C[m,n] = sum_k A[m,k]*W[n,k] + bias[n] ----------------
// Tile 128x128, BK=16, 128 threads, 16x8 per-thread microtile.
// Accumulators packed along m (f32x2 pairs) so the a-operand needs no dup.
__global__ void __launch_bounds__(128, 2) gemm_nt_bias(
    const float* __restrict__ A, const float* __restrict__ W,
    const float* __restrict__ bias, float* __restrict__ C,
    int K, int N)
{
    __shared__ __align__(16) float As[2][16][128];
    __shared__ __align__(16) float Ws[2][16][128];

    const int tid = threadIdx.x;
    const int m0 = blockIdx.x * 128;
    const int n0 = blockIdx.y * 128;
    const int tx = tid & 15;     // n micro-tile index (8 cols each)
    const int ty = tid >> 4;     // m micro-tile index (16 rows each)

    const float* Ap  = A + (size_t)(m0 + tid) * K;
    const float* Wpg = W + (size_t)(n0 + tid) * K;

    // acc[mp][n4]: mp = m-pair 0..7 (m = ty*16 + 2*mp + lane), n4 = 0..7 (n = tx*8 + ... )
    // layout: acc[mp][j] covers m-pair mp, single n column j? -> use [8][8] ULL:
    // acc[mp][j] is f32x2 over (m=2mp, m=2mp+1) at column n0+tx*8+j.
    ull acc[8][8];
#pragma unroll
    for (int i = 0; i < 8; i++)
#pragma unroll
        for (int j = 0; j < 8; j++) acc[i][j] = 0ull;

    const int nst = K >> 4;
    float4 ra[4], rw[4];
#pragma unroll
    for (int j = 0; j < 4; j++) {
        ra[j] = *(const float4*)(Ap + 4 * j);
        rw[j] = *(const float4*)(Wpg + 4 * j);
    }

    auto sts = [&](int buf) {
#pragma unroll
        for (int j = 0; j < 4; j++) {
            As[buf][4 * j + 0][tid] = ra[j].x;
            As[buf][4 * j + 1][tid] = ra[j].y;
            As[buf][4 * j + 2][tid] = ra[j].z;
            As[buf][4 * j + 3][tid] = ra[j].w;
            Ws[buf][4 * j + 0][tid] = rw[j].x;
            Ws[buf][4 * j + 1][tid] = rw[j].y;
            Ws[buf][4 * j + 2][tid] = rw[j].z;
            Ws[buf][4 * j + 3][tid] = rw[j].w;
        }
    };

    sts(0);
    __syncthreads();

    for (int ks = 0; ks < nst; ks++) {
        const int cur = ks & 1;
        if (ks + 1 < nst) {
            const float* a2 = Ap + (ks + 1) * 16;
            const float* w2 = Wpg + (ks + 1) * 16;
#pragma unroll
            for (int j = 0; j < 4; j++) {
                ra[j] = *(const float4*)(a2 + 4 * j);
                rw[j] = *(const float4*)(w2 + 4 * j);
            }
        }
#pragma unroll
        for (int k = 0; k < 16; k++) {
            // a: 16 m-values = 8 f32x2 pairs, loaded as 4 x float4 (reg pairs are free)
            const float4* arow = (const float4*)&As[cur][k][ty * 16];
            float4 a0 = arow[0], a1 = arow[1], a2 = arow[2], a3 = arow[3];
            ull ap[8];
            ap[0] = pk2(a0.x, a0.y); ap[1] = pk2(a0.z, a0.w);
            ap[2] = pk2(a1.x, a1.y); ap[3] = pk2(a1.z, a1.w);
            ap[4] = pk2(a2.x, a2.y); ap[5] = pk2(a2.z, a2.w);
            ap[6] = pk2(a3.x, a3.y); ap[7] = pk2(a3.z, a3.w);
            // b: 8 n-values, duplicated
            const float4* brow = (const float4*)&Ws[cur][k][tx * 8];
            float4 b0 = brow[0], b1 = brow[1];
            ull bd[8];
            bd[0] = dup2(b0.x); bd[1] = dup2(b0.y);
            bd[2] = dup2(b0.z); bd[3] = dup2(b0.w);
            bd[4] = dup2(b1.x); bd[5] = dup2(b1.y);
            bd[6] = dup2(b1.z); bd[7] = dup2(b1.w);
#pragma unroll
            for (int i = 0; i < 8; i++)
#pragma unroll
                for (int j = 0; j < 8; j++)
                    fma2p(acc[i][j], ap[i], bd[j]);
        }
        if (ks + 1 < nst) {
            sts(cur ^ 1);
            __syncthreads();
        }
    }

    float bs[8];
#pragma unroll
    for (int j = 0; j < 8; j++) bs[j] = bias[n0 + tx * 8 + j];
#pragma unroll
    for (int i = 0; i < 8; i++) {
        float2 p[8];
#pragma unroll
        for (int j = 0; j < 8; j++) p[j] = upk(acc[i][j]);
        float* cp0 = C + (size_t)(m0 + ty * 16 + 2 * i) * N + n0 + tx * 8;
        float* cp1 = cp0 + N;
        float4 e0 = make_float4(p[0].x + bs[0], p[1].x + bs[1], p[2].x + bs[2], p[3].x + bs[3]);
        float4 e1 = make_float4(p[4].x + bs[4], p[5].x + bs[5], p[6].x + bs[6], p[7].x + bs[7]);
        float4 o0 = make_float4(p[0].y + bs[0], p[1].y + bs[1], p[2].y + bs[2], p[3].y + bs[3]);
        float4 o1 = make_float4(p[4].y + bs[4], p[5].y + bs[5], p[6].y + bs[6], p[7].y + bs[7]);
        *(float4*)cp0 = e0;
        *(float4*)(cp0 + 4) = e1;
        *(float4*)cp1 = o0;
        *(float4*)(cp1 + 4) = o1;
    }
}

// ---------------- GRU recurrence: one CTA per sequence ----------------
// 384 threads; thread g owns Whh[g,0:128] in regs.  h loaded via LDS.128
// (broadcast).  xg never staged in smem: r/z rows fold their own xg value
// into the dot's bias; n rows pass xn via a 128-float smem slot (tanh needs
// xn OUTSIDE the r*hn product).
template <bool LAST>
__global__ void __launch_bounds__(384, 1) gru_layer_kernel(
    const float* __restrict__ xg,   // [Bv,Sv,3H]
    const float* __restrict__ Whh,  // [3H,H]
    const float* __restrict__ bhh,  // [3H]
    const int* __restrict__ len,
    float* __restrict__ h_out,      // [Bv,Sv,H] when !LAST
    float* __restrict__ out,        // [Bv,H] when LAST (sorted order)
    const int* __restrict__ rank)
{
    const int b = blockIdx.x;
    const int g = threadIdx.x;

    __shared__ __align__(16) float h_sh[Hv];
    __shared__ float hg_sh[G3];
    __shared__ float xn_sh[Hv];

    ull w[64];
    {
        const float4* wp = (const float4*)(Whh + (size_t)g * Hv);
#pragma unroll
        for (int i = 0; i < 32; i++) {
            float4 v = wp[i];
            w[2 * i]     = pk2(v.x, v.y);
            w[2 * i + 1] = pk2(v.z, v.w);
        }
    }
    const float bh = bhh[g];
    const int L = len[b];
    const float* xb = xg + (size_t)b * Sv * G3 + g;
    const bool is_n_row = (g >= 2 * Hv);

    if (g < Hv) h_sh[g] = 0.0f;
    float x0 = (L > 0) ? xb[0] : 0.0f;
    float x1 = (L > 1) ? xb[G3] : 0.0f;
    __syncthreads();

    float oacc = 0.0f;

    for (int s = 0; s < L; s++) {
        float xN = (s + 2 < L) ? xb[(size_t)(s + 2) * G3] : 0.0f;

        ull a0 = pk2(is_n_row ? bh : (bh + x0), 0.0f);
        ull a1 = 0ull;
        const ulonglong2* hp = (const ulonglong2*)h_sh;
#pragma unroll
        for (int i = 0; i < 32; i++) {
            ulonglong2 hv = hp[i];
            fma2p(a0, w[2 * i],     hv.x);
            fma2p(a1, w[2 * i + 1], hv.y);
        }
        float2 f0 = upk(a0), f1 = upk(a1);
        if (is_n_row) xn_sh[g - 2 * Hv] = x0;
        hg_sh[g] = (f0.x + f1.x) + (f0.y + f1.y);
        __syncthreads();

        if (g < Hv) {
            float r = fsig(hg_sh[g]);
            float z = fsig(hg_sh[g + Hv]);
            float n = ftanh(xn_sh[g] + r * hg_sh[g + 2 * Hv]);
            float hprev = h_sh[g];
            float hnew = n + z * (hprev - n);
            h_sh[g] = hnew;
            if (!LAST) {
                h_out[((size_t)b * Sv + s) * Hv + g] = hnew;
            } else {
                oacc += hnew;
            }
        }
        __syncthreads();
        x0 = x1;
        x1 = xN;
    }

    if (LAST && g < Hv) {
        out[(size_t)rank[b] * Hv + g] = oacc * (1.0f / (float)Sv);
    }
}

// ---------------- launch ----------------
extern "C" void kernel_launch(void* const* d_in, const int* in_sizes, int n_in,
                              void* d_out, int out_size) {
    (void)in_sizes; (void)n_in; (void)out_size;
    const float* x    = (const float*)d_in[0];
    const float* Wp   = (const float*)d_in[1];
    const float* bp   = (const float*)d_in[2];
    const float* Wih0 = (const float*)d_in[3];
    const float* Whh0 = (const float*)d_in[4];
    const float* bih0 = (const float*)d_in[5];
    const float* bhh0 = (const float*)d_in[6];
    const float* Wih1 = (const float*)d_in[7];
    const float* Whh1 = (const float*)d_in[8];
    const float* bih1 = (const float*)d_in[9];
    const float* bhh1 = (const float*)d_in[10];
    float* out = (float*)d_out;

    float *xg, *proj;
    int *len, *rank;
    cudaGetSymbolAddress((void**)&xg, g_xg);
    cudaGetSymbolAddress((void**)&proj, g_proj);
    cudaGetSymbolAddress((void**)&len, g_len);
    cudaGetSymbolAddress((void**)&rank, g_rank);

    const int M = Bv * Sv;

    lengths_kernel<<<Bv, 256>>>(x, len);
    rank_kernel<<<1, Bv>>>(len, rank);
    // proj = x @ Wp^T + bp        [M,512] x [128,512] -> [M,128]
    gemm_nt_bias<<<dim3(M / 128, Hv / 128), 128>>>(x, Wp, bp, proj, Fv, Hv);
    // xg0 = proj @ Wih0^T + bih0  [M,128] x [384,128] -> [M,384]
    gemm_nt_bias<<<dim3(M / 128, G3 / 128), 128>>>(proj, Wih0, bih0, xg, Hv, G3);
    // layer 0 recurrence: writes h1 into proj buffer (proj no longer needed)
    gru_layer_kernel<false><<<Bv, 384>>>(xg, Whh0, bhh0, len, proj, nullptr, nullptr);
    // xg1 = h1 @ Wih1^T + bih1
    gemm_nt_bias<<<dim3(M / 128, G3 / 128), 128>>>(proj, Wih1, bih1, xg, Hv, G3);
    // layer 1 recurrence: accumulates masked mean, scatters by rank
    gru_layer_kernel<true><<<Bv, 384>>>(xg, Whh1, bhh1, len, nullptr, out, rank);
}